// round 4
// baseline (speedup 1.0000x reference)
#include <cuda_runtime.h>

#define BB 2048
#define TT 512
#define DD 32
#define HH 16

// Scratch (device globals: allocation-guard-safe)
__device__ float g_x[(size_t)TT * BB * HH];   // pre-net output, layout [t][b][h]
__device__ float g_h[BB * HH];
__device__ float g_c[BB * HH];

__device__ __forceinline__ float ex2f_(float x){ float y; asm("ex2.approx.f32 %0, %1;" : "=f"(y) : "f"(x)); return y; }
__device__ __forceinline__ float rcpf_(float x){ float y; asm("rcp.approx.f32 %0, %1;" : "=f"(y) : "f"(x)); return y; }

#define L2E 1.4426950408889634f

// v = 1 - m * rcp(1 + 2^(s*x)) : sigmoid for (s=L2E, m=1), tanh for (s=2*L2E, m=2).
// Safe for +/-inf arguments (rcp(inf)=0).
__device__ __forceinline__ float gate_act(float x, float s, float m){
    return fmaf(-m, rcpf_(1.0f + ex2f_(s * x)), 1.0f);
}

// ---------------------------------------------------------------------------
// Kernel 1: pre-net  x = (leaky(leaky(seq@W1^T+b1)@W2^T+b2))@W3^T+b3
// thread-per-(b,t) row, weights broadcast from smem.
// ---------------------------------------------------------------------------
__global__ __launch_bounds__(256) void prenet_kernel(
    const float* __restrict__ seq,
    const float* __restrict__ w1, const float* __restrict__ b1,
    const float* __restrict__ w2, const float* __restrict__ b2,
    const float* __restrict__ w3, const float* __restrict__ b3)
{
    __shared__ float sw1[HH*DD], sw2[HH*HH], sw3[HH*HH], sb[3*HH];
    int tid = threadIdx.x;
    for (int i = tid; i < HH*DD; i += 256) sw1[i] = w1[i];
    for (int i = tid; i < HH*HH; i += 256) sw2[i] = w2[i];
    for (int i = tid; i < HH*HH; i += 256) sw3[i] = w3[i];
    if (tid < HH) { sb[tid] = b1[tid]; sb[HH+tid] = b2[tid]; sb[2*HH+tid] = b3[tid]; }
    __syncthreads();

    int row = blockIdx.x * 256 + tid;       // row in [0, B*T)
    int b = row & (BB - 1);
    int t = row >> 11;                      // B = 2^11

    const float4* sp = reinterpret_cast<const float4*>(seq) + ((size_t)b*TT + t)*(DD/4);
    float in[DD];
#pragma unroll
    for (int i = 0; i < DD/4; i++){ float4 v = sp[i]; in[4*i]=v.x; in[4*i+1]=v.y; in[4*i+2]=v.z; in[4*i+3]=v.w; }

    float y1[HH];
#pragma unroll
    for (int j = 0; j < HH; j++){
        float a = sb[j];
#pragma unroll
        for (int k = 0; k < DD; k++) a = fmaf(sw1[j*DD+k], in[k], a);
        y1[j] = fmaxf(a, 0.01f*a);
    }
    float y2[HH];
#pragma unroll
    for (int j = 0; j < HH; j++){
        float a = sb[HH+j];
#pragma unroll
        for (int k = 0; k < HH; k++) a = fmaf(sw2[j*HH+k], y1[k], a);
        y2[j] = fmaxf(a, 0.01f*a);
    }
    float y3[HH];
#pragma unroll
    for (int j = 0; j < HH; j++){
        float a = sb[2*HH+j];
#pragma unroll
        for (int k = 0; k < HH; k++) a = fmaf(sw3[j*HH+k], y2[k], a);
        y3[j] = a;                      // NO leaky on layer 3
    }

    float4* xp = reinterpret_cast<float4*>(g_x) + ((size_t)t*BB + b)*(HH/4);
    xp[0] = make_float4(y3[0],  y3[1],  y3[2],  y3[3]);
    xp[1] = make_float4(y3[4],  y3[5],  y3[6],  y3[7]);
    xp[2] = make_float4(y3[8],  y3[9],  y3[10], y3[11]);
    xp[3] = make_float4(y3[12], y3[13], y3[14], y3[15]);
}

// ---------------------------------------------------------------------------
// Kernel 2: encoder LSTM. One warp per batch element, 2048 warps resident.
// lane (0..15): gate rows g (i) and 16+g (f);  lane (16..31): 32+g (g), 48+g (o)
// ---------------------------------------------------------------------------
__global__ __launch_bounds__(128, 4) void encoder_kernel(
    const float* __restrict__ Wih, const float* __restrict__ Whh,
    const float* __restrict__ bih, const float* __restrict__ bhh)
{
    __shared__ __align__(16) float hb[4][HH];
    int tid  = threadIdx.x;
    int w    = tid >> 5, lane = tid & 31;
    int g    = lane & 15, half = lane >> 4;
    int b    = blockIdx.x * 4 + w;

    int r0 = half ? (2*HH + g) : g;
    int r1 = half ? (3*HH + g) : (HH + g);

    float wi0[HH], wi1[HH], wh0[HH], wh1[HH];
    {
        const float4* p0 = reinterpret_cast<const float4*>(Wih + r0*HH);
        const float4* p1 = reinterpret_cast<const float4*>(Wih + r1*HH);
        const float4* q0 = reinterpret_cast<const float4*>(Whh + r0*HH);
        const float4* q1 = reinterpret_cast<const float4*>(Whh + r1*HH);
#pragma unroll
        for (int i = 0; i < 4; i++){
            float4 v;
            v = p0[i]; wi0[4*i]=v.x; wi0[4*i+1]=v.y; wi0[4*i+2]=v.z; wi0[4*i+3]=v.w;
            v = p1[i]; wi1[4*i]=v.x; wi1[4*i+1]=v.y; wi1[4*i+2]=v.z; wi1[4*i+3]=v.w;
            v = q0[i]; wh0[4*i]=v.x; wh0[4*i+1]=v.y; wh0[4*i+2]=v.z; wh0[4*i+3]=v.w;
            v = q1[i]; wh1[4*i]=v.x; wh1[4*i+1]=v.y; wh1[4*i+2]=v.z; wh1[4*i+3]=v.w;
        }
    }
    float bg0 = bih[r0] + bhh[r0];
    float bg1 = bih[r1] + bhh[r1];
    float s0 = half ? 2.0f*L2E : L2E;     // acc0: tanh on upper half (g-gate), sigmoid lower (i)
    float m0 = half ? 2.0f : 1.0f;        // acc1 is always sigmoid (f / o)

    float hvec[HH];
#pragma unroll
    for (int k = 0; k < HH; k++) hvec[k] = 0.0f;
    float c = 0.0f, h = 0.0f;

    const float4* xbase = reinterpret_cast<const float4*>(g_x);
    float4 cx0, cx1, cx2, cx3;
    { const float4* p = xbase + (size_t)b*(HH/4); cx0=p[0]; cx1=p[1]; cx2=p[2]; cx3=p[3]; }

#pragma unroll 1
    for (int t = 0; t < TT; t++){
        // prefetch next step's x (hides L2 latency)
        int tn = (t + 1 < TT) ? t + 1 : t;
        const float4* pn = xbase + ((size_t)tn*BB + b)*(HH/4);
        float4 nx0 = pn[0], nx1 = pn[1], nx2 = pn[2], nx3 = pn[3];

        float xv[HH];
        xv[0]=cx0.x; xv[1]=cx0.y; xv[2]=cx0.z; xv[3]=cx0.w;
        xv[4]=cx1.x; xv[5]=cx1.y; xv[6]=cx1.z; xv[7]=cx1.w;
        xv[8]=cx2.x; xv[9]=cx2.y; xv[10]=cx2.z; xv[11]=cx2.w;
        xv[12]=cx3.x; xv[13]=cx3.y; xv[14]=cx3.z; xv[15]=cx3.w;

        float a0 = bg0, a1 = bg1;
#pragma unroll
        for (int k = 0; k < HH; k++){
            a0 = fmaf(wi0[k], xv[k],   a0);
            a1 = fmaf(wi1[k], xv[k],   a1);
            a0 = fmaf(wh0[k], hvec[k], a0);
            a1 = fmaf(wh1[k], hvec[k], a1);
        }
        float v0 = gate_act(a0, s0, m0);          // i (low half) / g (high half)
        float v1 = gate_act(a1, L2E, 1.0f);       // f (low half) / o (high half)
        float gg = __shfl_xor_sync(0xffffffffu, v0, 16);
        float oo = __shfl_xor_sync(0xffffffffu, v1, 16);
        // valid on lanes 0..15: i=v0 f=v1 g=gg o=oo
        c = fmaf(v1, c, v0 * gg);
        float th = gate_act(c, 2.0f*L2E, 2.0f);
        h = oo * th;

        if (!half) hb[w][g] = h;
        __syncwarp();
        {
            const float4* hp = reinterpret_cast<const float4*>(hb[w]);
            float4 h0 = hp[0], h1 = hp[1], h2 = hp[2], h3 = hp[3];
            hvec[0]=h0.x; hvec[1]=h0.y; hvec[2]=h0.z; hvec[3]=h0.w;
            hvec[4]=h1.x; hvec[5]=h1.y; hvec[6]=h1.z; hvec[7]=h1.w;
            hvec[8]=h2.x; hvec[9]=h2.y; hvec[10]=h2.z; hvec[11]=h2.w;
            hvec[12]=h3.x; hvec[13]=h3.y; hvec[14]=h3.z; hvec[15]=h3.w;
        }
        __syncwarp();
        cx0 = nx0; cx1 = nx1; cx2 = nx2; cx3 = nx3;
    }
    if (!half){ g_h[b*HH + g] = h; g_c[b*HH + g] = c; }
}

// ---------------------------------------------------------------------------
// Kernel 3: decoder. Same warp-per-batch layout. h2l/post weights in smem
// (transposed, conflict-free broadcast) to stay under 128 regs/thread.
// ---------------------------------------------------------------------------
__global__ __launch_bounds__(128, 4) void decoder_kernel(
    const float* __restrict__ Wih, const float* __restrict__ Whh,
    const float* __restrict__ bih, const float* __restrict__ bhh,
    const float* __restrict__ h2l_w1, const float* __restrict__ h2l_b1,
    const float* __restrict__ h2l_w2, const float* __restrict__ h2l_b2,
    const float* __restrict__ post_w, const float* __restrict__ post_b,
    float* __restrict__ out, int dup)
{
    __shared__ __align__(16) float w1t[HH*HH];     // w1t[k*16+j] = h2l_w1[j][k]
    __shared__ __align__(16) float w2t[HH*HH];
    __shared__ __align__(16) float pwt[HH*DD];     // pwt[k*32+d] = post_w[d][k]
    __shared__ __align__(16) float hb[4][HH];
    __shared__ __align__(16) float sb2[4][HH];

    int tid  = threadIdx.x;
    for (int i = tid; i < HH*HH; i += 128){ int j = i >> 4, k = i & 15; w1t[k*HH + j] = h2l_w1[i]; w2t[k*HH + j] = h2l_w2[i]; }
    for (int i = tid; i < DD*HH; i += 128){ int d = i >> 4, k = i & 15; pwt[k*DD + d] = post_w[i]; }
    __syncthreads();

    int w    = tid >> 5, lane = tid & 31;
    int g    = lane & 15, half = lane >> 4;
    int b    = blockIdx.x * 4 + w;

    int r0 = half ? (2*HH + g) : g;
    int r1 = half ? (3*HH + g) : (HH + g);

    float wi0[HH], wi1[HH], wh0[HH], wh1[HH];
    {
        const float4* p0 = reinterpret_cast<const float4*>(Wih + r0*HH);
        const float4* p1 = reinterpret_cast<const float4*>(Wih + r1*HH);
        const float4* q0 = reinterpret_cast<const float4*>(Whh + r0*HH);
        const float4* q1 = reinterpret_cast<const float4*>(Whh + r1*HH);
#pragma unroll
        for (int i = 0; i < 4; i++){
            float4 v;
            v = p0[i]; wi0[4*i]=v.x; wi0[4*i+1]=v.y; wi0[4*i+2]=v.z; wi0[4*i+3]=v.w;
            v = p1[i]; wi1[4*i]=v.x; wi1[4*i+1]=v.y; wi1[4*i+2]=v.z; wi1[4*i+3]=v.w;
            v = q0[i]; wh0[4*i]=v.x; wh0[4*i+1]=v.y; wh0[4*i+2]=v.z; wh0[4*i+3]=v.w;
            v = q1[i]; wh1[4*i]=v.x; wh1[4*i+1]=v.y; wh1[4*i+2]=v.z; wh1[4*i+3]=v.w;
        }
    }
    float bg0 = bih[r0] + bhh[r0];
    float bg1 = bih[r1] + bhh[r1];
    float s0 = half ? 2.0f*L2E : L2E;
    float m0 = half ? 2.0f : 1.0f;
    float pb  = post_b[lane];          // d = lane, 0..31
    float hb1 = h2l_b1[g];
    float hb2 = h2l_b2[g];

    // initial state from encoder; start0 = pre-net output at t = T-1
    float c = g_c[b*HH + g];
    float h = g_h[b*HH + g];
    float hvec[HH], sv[HH];
    {
        const float4* hp = reinterpret_cast<const float4*>(g_h + b*HH);
        float4 h0 = hp[0], h1 = hp[1], h2 = hp[2], h3 = hp[3];
        hvec[0]=h0.x; hvec[1]=h0.y; hvec[2]=h0.z; hvec[3]=h0.w;
        hvec[4]=h1.x; hvec[5]=h1.y; hvec[6]=h1.z; hvec[7]=h1.w;
        hvec[8]=h2.x; hvec[9]=h2.y; hvec[10]=h2.z; hvec[11]=h2.w;
        hvec[12]=h3.x; hvec[13]=h3.y; hvec[14]=h3.z; hvec[15]=h3.w;
        const float4* xp = reinterpret_cast<const float4*>(g_x) + ((size_t)(TT-1)*BB + b)*(HH/4);
        float4 x0 = xp[0], x1 = xp[1], x2 = xp[2], x3 = xp[3];
        sv[0]=x0.x; sv[1]=x0.y; sv[2]=x0.z; sv[3]=x0.w;
        sv[4]=x1.x; sv[5]=x1.y; sv[6]=x1.z; sv[7]=x1.w;
        sv[8]=x2.x; sv[9]=x2.y; sv[10]=x2.z; sv[11]=x2.w;
        sv[12]=x3.x; sv[13]=x3.y; sv[14]=x3.z; sv[15]=x3.w;
    }

    float* outp = out + ((size_t)b*TT)*DD + lane;
    const size_t dupoff = (size_t)BB*TT*DD;

#pragma unroll 1
    for (int s = 0; s < TT; s++){
        // LSTM cell: input = sv (current 'start'), state hvec/c
        float a0 = bg0, a1 = bg1;
#pragma unroll
        for (int k = 0; k < HH; k++){
            a0 = fmaf(wi0[k], sv[k],   a0);
            a1 = fmaf(wi1[k], sv[k],   a1);
            a0 = fmaf(wh0[k], hvec[k], a0);
            a1 = fmaf(wh1[k], hvec[k], a1);
        }
        float v0 = gate_act(a0, s0, m0);
        float v1 = gate_act(a1, L2E, 1.0f);
        float gg = __shfl_xor_sync(0xffffffffu, v0, 16);
        float oo = __shfl_xor_sync(0xffffffffu, v1, 16);
        c = fmaf(v1, c, v0 * gg);
        float th = gate_act(c, 2.0f*L2E, 2.0f);
        h = oo * th;

        // replicate new h
        if (!half) hb[w][g] = h;
        __syncwarp();
        {
            const float4* hp = reinterpret_cast<const float4*>(hb[w]);
            float4 h0 = hp[0], h1 = hp[1], h2 = hp[2], h3 = hp[3];
            hvec[0]=h0.x; hvec[1]=h0.y; hvec[2]=h0.z; hvec[3]=h0.w;
            hvec[4]=h1.x; hvec[5]=h1.y; hvec[6]=h1.z; hvec[7]=h1.w;
            hvec[8]=h2.x; hvec[9]=h2.y; hvec[10]=h2.z; hvec[11]=h2.w;
            hvec[12]=h3.x; hvec[13]=h3.y; hvec[14]=h3.z; hvec[15]=h3.w;
        }
        __syncwarp();

        // out = h @ post_w.T + post_b  (lane = output dim d)
        float ao = pb;
#pragma unroll
        for (int k = 0; k < HH; k++) ao = fmaf(hvec[k], pwt[k*DD + lane], ao);
        size_t oidx = (size_t)(TT - 1 - s) * DD;
        outp[oidx] = ao;
        if (dup) outp[oidx + dupoff] = ao;

        // s1 = leaky(h @ w1.T + b1)
        float as = hb1;
#pragma unroll
        for (int k = 0; k < HH; k++) as = fmaf(hvec[k], w1t[k*HH + g], as);
        as = fmaxf(as, 0.01f*as);
        if (!half) sb2[w][g] = as;
        __syncwarp();
        float s1v[HH];
        {
            const float4* sp = reinterpret_cast<const float4*>(sb2[w]);
            float4 t0 = sp[0], t1 = sp[1], t2 = sp[2], t3 = sp[3];
            s1v[0]=t0.x; s1v[1]=t0.y; s1v[2]=t0.z; s1v[3]=t0.w;
            s1v[4]=t1.x; s1v[5]=t1.y; s1v[6]=t1.z; s1v[7]=t1.w;
            s1v[8]=t2.x; s1v[9]=t2.y; s1v[10]=t2.z; s1v[11]=t2.w;
            s1v[12]=t3.x; s1v[13]=t3.y; s1v[14]=t3.z; s1v[15]=t3.w;
        }
        __syncwarp();

        // start = s1 @ w2.T + b2  (no leaky), then replicate
        float at = hb2;
#pragma unroll
        for (int k = 0; k < HH; k++) at = fmaf(s1v[k], w2t[k*HH + g], at);
        if (!half) sb2[w][g] = at;
        __syncwarp();
        {
            const float4* sp = reinterpret_cast<const float4*>(sb2[w]);
            float4 t0 = sp[0], t1 = sp[1], t2 = sp[2], t3 = sp[3];
            sv[0]=t0.x; sv[1]=t0.y; sv[2]=t0.z; sv[3]=t0.w;
            sv[4]=t1.x; sv[5]=t1.y; sv[6]=t1.z; sv[7]=t1.w;
            sv[8]=t2.x; sv[9]=t2.y; sv[10]=t2.z; sv[11]=t2.w;
            sv[12]=t3.x; sv[13]=t3.y; sv[14]=t3.z; sv[15]=t3.w;
        }
        __syncwarp();
    }
}

// ---------------------------------------------------------------------------
extern "C" void kernel_launch(void* const* d_in, const int* in_sizes, int n_in,
                              void* d_out, int out_size)
{
    const float* seq     = (const float*)d_in[0];
    const float* pre_w1  = (const float*)d_in[1];
    const float* pre_b1  = (const float*)d_in[2];
    const float* pre_w2  = (const float*)d_in[3];
    const float* pre_b2  = (const float*)d_in[4];
    const float* pre_w3  = (const float*)d_in[5];
    const float* pre_b3  = (const float*)d_in[6];
    const float* enc_Wih = (const float*)d_in[7];
    const float* enc_Whh = (const float*)d_in[8];
    const float* enc_bih = (const float*)d_in[9];
    const float* enc_bhh = (const float*)d_in[10];
    const float* h2l_w1  = (const float*)d_in[11];
    const float* h2l_b1  = (const float*)d_in[12];
    const float* h2l_w2  = (const float*)d_in[13];
    const float* h2l_b2  = (const float*)d_in[14];
    const float* post_w  = (const float*)d_in[15];
    const float* post_b  = (const float*)d_in[16];

    int dup = (out_size >= 2 * BB * TT * DD) ? 1 : 0;

    prenet_kernel<<<(BB*TT)/256, 256>>>(seq, pre_w1, pre_b1, pre_w2, pre_b2, pre_w3, pre_b3);
    encoder_kernel<<<BB/4, 128>>>(enc_Wih, enc_Whh, enc_bih, enc_bhh);
    decoder_kernel<<<BB/4, 128>>>(enc_Wih, enc_Whh, enc_bih, enc_bhh,
                                  h2l_w1, h2l_b1, h2l_w2, h2l_b2,
                                  post_w, post_b, (float*)d_out, dup);
}

// round 7
// speedup vs baseline: 1.0074x; 1.0074x over previous
#include <cuda_runtime.h>

#define BB 2048
#define TT 512
#define DD 32
#define HH 16
typedef unsigned long long u64;

// Scratch (device globals: allocation-guard-safe)
__device__ __align__(16) float g_x[(size_t)TT * BB * HH];   // pre-net output, [t][b][h]
__device__ __align__(16) float g_h[BB * HH];
__device__ __align__(16) float g_c[BB * HH];

__device__ __forceinline__ float ex2f_(float x){ float y; asm("ex2.approx.f32 %0, %1;" : "=f"(y) : "f"(x)); return y; }
__device__ __forceinline__ float rcpf_(float x){ float y; asm("rcp.approx.f32 %0, %1;" : "=f"(y) : "f"(x)); return y; }

#define L2E 1.4426950408889634f

// v = 1 - m * rcp(1 + 2^(s*x)) : sigmoid (s=L2E,m=1), tanh (s=2*L2E,m=2)
__device__ __forceinline__ float gate_act(float x, float s, float m){
    return fmaf(-m, rcpf_(1.0f + ex2f_(s * x)), 1.0f);
}

// ---- f32x2 packed helpers (FFMA2 is PTX-only; ptxas won't fuse from C++) ----
__device__ __forceinline__ u64 pack2(float lo, float hi){ u64 r; asm("mov.b64 %0, {%1,%2};" : "=l"(r) : "f"(lo), "f"(hi)); return r; }
__device__ __forceinline__ void unpack2(u64 v, float& lo, float& hi){ asm("mov.b64 {%0,%1}, %2;" : "=f"(lo), "=f"(hi) : "l"(v)); }
__device__ __forceinline__ u64 fma2(u64 a, u64 b, u64 c){ u64 d; asm("fma.rn.f32x2 %0, %1, %2, %3;" : "=l"(d) : "l"(a), "l"(b), "l"(c)); return d; }
__device__ __forceinline__ u64 add2(u64 a, u64 b){ u64 d; asm("add.rn.f32x2 %0, %1, %2;" : "=l"(d) : "l"(a), "l"(b)); return d; }
__device__ __forceinline__ float hsum2(u64 a){ float lo, hi; unpack2(a, lo, hi); return lo + hi; }
__device__ __forceinline__ u64 leaky2(u64 a){
    float lo, hi; unpack2(a, lo, hi);
    lo = fmaxf(lo, 0.01f*lo); hi = fmaxf(hi, 0.01f*hi);
    return pack2(lo, hi);
}

// ---------------------------------------------------------------------------
// Kernel 1: pre-net. Each thread handles TWO rows (b,t) and (b,t+256), packed
// as f32x2. Weights stored in smem as broadcast pairs {w,w}, fetched 2/LDS.128.
//   -> FMA-instr/row halved, LDS/row quartered (fixes the 90.6% L1 bound).
// ---------------------------------------------------------------------------
__global__ __launch_bounds__(256) void prenet_kernel(
    const float* __restrict__ seq,
    const float* __restrict__ w1, const float* __restrict__ b1,
    const float* __restrict__ w2, const float* __restrict__ b2,
    const float* __restrict__ w3, const float* __restrict__ b3)
{
    __shared__ __align__(16) u64 sw1[HH*DD];   // broadcast-packed {w,w}
    __shared__ __align__(16) u64 sw2[HH*HH];
    __shared__ __align__(16) u64 sw3[HH*HH];
    __shared__ __align__(16) u64 sbp[3*HH];

    int tid = threadIdx.x;
    for (int i = tid; i < HH*DD; i += 256){ float v = w1[i]; sw1[i] = pack2(v, v); }
    for (int i = tid; i < HH*HH; i += 256){ float v = w2[i]; sw2[i] = pack2(v, v);
                                            float u = w3[i]; sw3[i] = pack2(u, u); }
    if (tid < HH){
        float v = b1[tid]; sbp[tid]       = pack2(v, v);
        v = b2[tid];       sbp[HH+tid]    = pack2(v, v);
        v = b3[tid];       sbp[2*HH+tid]  = pack2(v, v);
    }
    __syncthreads();

    int r = blockIdx.x * 256 + tid;        // 0 .. B*T/2-1
    int b = r & (BB - 1);
    int t = r >> 11;                       // 0..255; pair row is t+256

    const float4* rowA = reinterpret_cast<const float4*>(seq + ((size_t)b*TT + t)*DD);
    const float4* rowB = reinterpret_cast<const float4*>(seq + ((size_t)b*TT + t + 256)*DD);

    u64 inP[DD];
#pragma unroll
    for (int i = 0; i < DD/4; i++){
        float4 a = rowA[i], c = rowB[i];
        inP[4*i+0] = pack2(a.x, c.x); inP[4*i+1] = pack2(a.y, c.y);
        inP[4*i+2] = pack2(a.z, c.z); inP[4*i+3] = pack2(a.w, c.w);
    }

    u64 y1[HH];
#pragma unroll
    for (int j = 0; j < HH; j++){
        u64 acc = sbp[j], acc2 = 0ULL;
        const ulonglong2* wp = reinterpret_cast<const ulonglong2*>(&sw1[j*DD]);
#pragma unroll
        for (int k = 0; k < DD/2; k++){
            ulonglong2 wv = wp[k];
            acc  = fma2(wv.x, inP[2*k],   acc);
            acc2 = fma2(wv.y, inP[2*k+1], acc2);
        }
        y1[j] = leaky2(add2(acc, acc2));
    }
    u64 y2[HH];
#pragma unroll
    for (int j = 0; j < HH; j++){
        u64 acc = sbp[HH+j], acc2 = 0ULL;
        const ulonglong2* wp = reinterpret_cast<const ulonglong2*>(&sw2[j*HH]);
#pragma unroll
        for (int k = 0; k < HH/2; k++){
            ulonglong2 wv = wp[k];
            acc  = fma2(wv.x, y1[2*k],   acc);
            acc2 = fma2(wv.y, y1[2*k+1], acc2);
        }
        y2[j] = leaky2(add2(acc, acc2));
    }
    float ya[HH], yb[HH];
#pragma unroll
    for (int j = 0; j < HH; j++){
        u64 acc = sbp[2*HH+j], acc2 = 0ULL;
        const ulonglong2* wp = reinterpret_cast<const ulonglong2*>(&sw3[j*HH]);
#pragma unroll
        for (int k = 0; k < HH/2; k++){
            ulonglong2 wv = wp[k];
            acc  = fma2(wv.x, y2[2*k],   acc);
            acc2 = fma2(wv.y, y2[2*k+1], acc2);
        }
        unpack2(add2(acc, acc2), ya[j], yb[j]);   // NO leaky on layer 3
    }

    float4* xa = reinterpret_cast<float4*>(g_x + ((size_t)t*BB + b)*HH);
    float4* xb = reinterpret_cast<float4*>(g_x + ((size_t)(t+256)*BB + b)*HH);
#pragma unroll
    for (int i = 0; i < 4; i++){
        xa[i] = make_float4(ya[4*i], ya[4*i+1], ya[4*i+2], ya[4*i+3]);
        xb[i] = make_float4(yb[4*i], yb[4*i+1], yb[4*i+2], yb[4*i+3]);
    }
}

// ---------------------------------------------------------------------------
// Kernel 2: encoder LSTM. One warp per batch element, 1-warp CTAs (2048 CTAs,
// 14/13 warps per SM). Gate matvecs as k-packed FFMA2, h round-trip via smem
// (double-buffered, single syncwarp).
// ---------------------------------------------------------------------------
__global__ __launch_bounds__(32, 14) void encoder_kernel(
    const float* __restrict__ Wih, const float* __restrict__ Whh,
    const float* __restrict__ bih, const float* __restrict__ bhh)
{
    __shared__ __align__(16) float hb[2][HH];
    int lane = threadIdx.x;
    int g    = lane & 15, half = lane >> 4;
    int b    = blockIdx.x;

    int r0 = half ? (2*HH + g) : g;          // i (low) / g (high)
    int r1 = half ? (3*HH + g) : (HH + g);   // f (low) / o (high)

    u64 wiP0[8], wiP1[8], whP0[8], whP1[8];
    {
        const ulonglong2* p0 = reinterpret_cast<const ulonglong2*>(Wih + r0*HH);
        const ulonglong2* p1 = reinterpret_cast<const ulonglong2*>(Wih + r1*HH);
        const ulonglong2* q0 = reinterpret_cast<const ulonglong2*>(Whh + r0*HH);
        const ulonglong2* q1 = reinterpret_cast<const ulonglong2*>(Whh + r1*HH);
#pragma unroll
        for (int i = 0; i < 4; i++){
            ulonglong2 v;
            v = p0[i]; wiP0[2*i] = v.x; wiP0[2*i+1] = v.y;
            v = p1[i]; wiP1[2*i] = v.x; wiP1[2*i+1] = v.y;
            v = q0[i]; whP0[2*i] = v.x; whP0[2*i+1] = v.y;
            v = q1[i]; whP1[2*i] = v.x; whP1[2*i+1] = v.y;
        }
    }
    u64 bg0P = pack2(bih[r0] + bhh[r0], 0.0f);
    u64 bg1P = pack2(bih[r1] + bhh[r1], 0.0f);
    float s0 = half ? 2.0f*L2E : L2E;
    float m0 = half ? 2.0f : 1.0f;

    u64 hP[8];
#pragma unroll
    for (int k = 0; k < 8; k++) hP[k] = 0ULL;
    float c = 0.0f, h = 0.0f;

    u64 xP[8];
    {
        const ulonglong2* p = reinterpret_cast<const ulonglong2*>(g_x + (size_t)b*HH);
        ulonglong2 v;
        v = p[0]; xP[0]=v.x; xP[1]=v.y;  v = p[1]; xP[2]=v.x; xP[3]=v.y;
        v = p[2]; xP[4]=v.x; xP[5]=v.y;  v = p[3]; xP[6]=v.x; xP[7]=v.y;
    }

#pragma unroll 1
    for (int t = 0; t < TT; t++){
        u64 pA = bg0P, qA = 0ULL, pB = bg1P, qB = 0ULL;
#pragma unroll
        for (int k = 0; k < 8; k += 2){
            pA = fma2(wiP0[k],   xP[k],   pA);
            qA = fma2(wiP0[k+1], xP[k+1], qA);
            pB = fma2(wiP1[k],   xP[k],   pB);
            qB = fma2(wiP1[k+1], xP[k+1], qB);
            pA = fma2(whP0[k],   hP[k],   pA);
            qA = fma2(whP0[k+1], hP[k+1], qA);
            pB = fma2(whP1[k],   hP[k],   pB);
            qB = fma2(whP1[k+1], hP[k+1], qB);
        }
        // prefetch next x (L2-resident) — xP dead after the accum above
        {
            int tn = (t + 1 < TT) ? t + 1 : t;
            const ulonglong2* pn = reinterpret_cast<const ulonglong2*>(g_x + ((size_t)tn*BB + b)*HH);
            ulonglong2 v;
            v = pn[0]; xP[0]=v.x; xP[1]=v.y;  v = pn[1]; xP[2]=v.x; xP[3]=v.y;
            v = pn[2]; xP[4]=v.x; xP[5]=v.y;  v = pn[3]; xP[6]=v.x; xP[7]=v.y;
        }
        float a0 = hsum2(add2(pA, qA));
        float a1 = hsum2(add2(pB, qB));
        float v0 = gate_act(a0, s0, m0);          // i / g
        float v1 = gate_act(a1, L2E, 1.0f);       // f / o
        float gg = __shfl_xor_sync(0xffffffffu, v0, 16);
        float oo = __shfl_xor_sync(0xffffffffu, v1, 16);
        c = fmaf(v1, c, v0 * gg);
        float th = gate_act(c, 2.0f*L2E, 2.0f);
        h = oo * th;

        int ph = t & 1;
        if (!half) hb[ph][g] = h;
        __syncwarp();
        {
            const ulonglong2* hp = reinterpret_cast<const ulonglong2*>(hb[ph]);
            ulonglong2 v;
            v = hp[0]; hP[0]=v.x; hP[1]=v.y;  v = hp[1]; hP[2]=v.x; hP[3]=v.y;
            v = hp[2]; hP[4]=v.x; hP[5]=v.y;  v = hp[3]; hP[6]=v.x; hP[7]=v.y;
        }
    }
    if (!half){ g_h[b*HH + g] = h; g_c[b*HH + g] = c; }
}

// ---------------------------------------------------------------------------
// Kernel 3: decoder. 1-warp CTAs. k-packed FFMA2 for all four matvecs; h2l/post
// weights in smem as k-packed u64 with row stride 9 (conflict-free for 16-row,
// 2-way for 32-row). 3 syncwarps/step (down from 6).
// ---------------------------------------------------------------------------
__global__ __launch_bounds__(32, 14) void decoder_kernel(
    const float* __restrict__ Wih, const float* __restrict__ Whh,
    const float* __restrict__ bih, const float* __restrict__ bhh,
    const float* __restrict__ h2l_w1, const float* __restrict__ h2l_b1,
    const float* __restrict__ h2l_w2, const float* __restrict__ h2l_b2,
    const float* __restrict__ post_w, const float* __restrict__ post_b,
    float* __restrict__ out, int dup)
{
    __shared__ __align__(16) u64 w1p[HH*9];      // {w1[j][2k],w1[j][2k+1]} at [j*9+k]
    __shared__ __align__(16) u64 w2p[HH*9];
    __shared__ __align__(16) u64 postp[DD*9];    // {pw[d][2k],pw[d][2k+1]} at [d*9+k]
    __shared__ __align__(16) float hbuf[HH];
    __shared__ __align__(16) float s1buf[HH];
    __shared__ __align__(16) float svbuf[HH];

    int lane = threadIdx.x;
    for (int i = lane; i < HH*8; i += 32){
        int j = i >> 3, k = i & 7;
        w1p[j*9+k] = pack2(h2l_w1[j*HH+2*k], h2l_w1[j*HH+2*k+1]);
        w2p[j*9+k] = pack2(h2l_w2[j*HH+2*k], h2l_w2[j*HH+2*k+1]);
    }
    for (int i = lane; i < DD*8; i += 32){
        int d = i >> 3, k = i & 7;
        postp[d*9+k] = pack2(post_w[d*HH+2*k], post_w[d*HH+2*k+1]);
    }
    __syncwarp();

    int g    = lane & 15, half = lane >> 4;
    int b    = blockIdx.x;

    int r0 = half ? (2*HH + g) : g;
    int r1 = half ? (3*HH + g) : (HH + g);

    u64 wiP0[8], wiP1[8], whP0[8], whP1[8];
    {
        const ulonglong2* p0 = reinterpret_cast<const ulonglong2*>(Wih + r0*HH);
        const ulonglong2* p1 = reinterpret_cast<const ulonglong2*>(Wih + r1*HH);
        const ulonglong2* q0 = reinterpret_cast<const ulonglong2*>(Whh + r0*HH);
        const ulonglong2* q1 = reinterpret_cast<const ulonglong2*>(Whh + r1*HH);
#pragma unroll
        for (int i = 0; i < 4; i++){
            ulonglong2 v;
            v = p0[i]; wiP0[2*i] = v.x; wiP0[2*i+1] = v.y;
            v = p1[i]; wiP1[2*i] = v.x; wiP1[2*i+1] = v.y;
            v = q0[i]; whP0[2*i] = v.x; whP0[2*i+1] = v.y;
            v = q1[i]; whP1[2*i] = v.x; whP1[2*i+1] = v.y;
        }
    }
    u64 bg0P = pack2(bih[r0] + bhh[r0], 0.0f);
    u64 bg1P = pack2(bih[r1] + bhh[r1], 0.0f);
    float s0 = half ? 2.0f*L2E : L2E;
    float m0 = half ? 2.0f : 1.0f;
    float pb  = post_b[lane];
    float hb1 = h2l_b1[g];
    float hb2 = h2l_b2[g];

    float c = g_c[b*HH + g];
    u64 hP[8], svP[8];
    {
        const ulonglong2* hp = reinterpret_cast<const ulonglong2*>(g_h + b*HH);
        ulonglong2 v;
        v = hp[0]; hP[0]=v.x; hP[1]=v.y;  v = hp[1]; hP[2]=v.x; hP[3]=v.y;
        v = hp[2]; hP[4]=v.x; hP[5]=v.y;  v = hp[3]; hP[6]=v.x; hP[7]=v.y;
        const ulonglong2* xp = reinterpret_cast<const ulonglong2*>(g_x + ((size_t)(TT-1)*BB + b)*HH);
        v = xp[0]; svP[0]=v.x; svP[1]=v.y;  v = xp[1]; svP[2]=v.x; svP[3]=v.y;
        v = xp[2]; svP[4]=v.x; svP[5]=v.y;  v = xp[3]; svP[6]=v.x; svP[7]=v.y;
    }

    float* outp = out + (size_t)b*TT*DD + lane;
    const size_t dupoff = (size_t)BB*TT*DD;
    const u64* w1r = &w1p[g*9];
    const u64* w2r = &w2p[g*9];
    const u64* pwr = &postp[lane*9];

#pragma unroll 1
    for (int s = 0; s < TT; s++){
        // LSTM gates from (svP, hP)
        u64 pA = bg0P, qA = 0ULL, pB = bg1P, qB = 0ULL;
#pragma unroll
        for (int k = 0; k < 8; k += 2){
            pA = fma2(wiP0[k],   svP[k],   pA);
            qA = fma2(wiP0[k+1], svP[k+1], qA);
            pB = fma2(wiP1[k],   svP[k],   pB);
            qB = fma2(wiP1[k+1], svP[k+1], qB);
            pA = fma2(whP0[k],   hP[k],    pA);
            qA = fma2(whP0[k+1], hP[k+1],  qA);
            pB = fma2(whP1[k],   hP[k],    pB);
            qB = fma2(whP1[k+1], hP[k+1],  qB);
        }
        float a0 = hsum2(add2(pA, qA));
        float a1 = hsum2(add2(pB, qB));
        float v0 = gate_act(a0, s0, m0);
        float v1 = gate_act(a1, L2E, 1.0f);
        float gg = __shfl_xor_sync(0xffffffffu, v0, 16);
        float oo = __shfl_xor_sync(0xffffffffu, v1, 16);
        c = fmaf(v1, c, v0 * gg);
        float th = gate_act(c, 2.0f*L2E, 2.0f);
        float h  = oo * th;

        // replicate h (single sync; WAR covered by later syncs in program order)
        if (!half) hbuf[g] = h;
        __syncwarp();
        {
            const ulonglong2* hp = reinterpret_cast<const ulonglong2*>(hbuf);
            ulonglong2 v;
            v = hp[0]; hP[0]=v.x; hP[1]=v.y;  v = hp[1]; hP[2]=v.x; hP[3]=v.y;
            v = hp[2]; hP[4]=v.x; hP[5]=v.y;  v = hp[3]; hP[6]=v.x; hP[7]=v.y;
        }

        // out = h @ post_w.T + post_b  (lane = d)
        {
            u64 po = 0ULL, qo = 0ULL;
#pragma unroll
            for (int k = 0; k < 8; k += 2){
                po = fma2(pwr[k],   hP[k],   po);
                qo = fma2(pwr[k+1], hP[k+1], qo);
            }
            float ao = pb + hsum2(add2(po, qo));
            size_t oidx = (size_t)(TT - 1 - s) * DD;
            outp[oidx] = ao;
            if (dup) outp[oidx + dupoff] = ao;
        }

        // s1 = leaky(h @ w1.T + b1)
        {
            u64 ps = 0ULL, qs = 0ULL;
#pragma unroll
            for (int k = 0; k < 8; k += 2){
                ps = fma2(w1r[k],   hP[k],   ps);
                qs = fma2(w1r[k+1], hP[k+1], qs);
            }
            float as = hb1 + hsum2(add2(ps, qs));
            as = fmaxf(as, 0.01f*as);
            if (!half) s1buf[g] = as;
        }
        __syncwarp();
        u64 s1P[8];
        {
            const ulonglong2* sp = reinterpret_cast<const ulonglong2*>(s1buf);
            ulonglong2 v;
            v = sp[0]; s1P[0]=v.x; s1P[1]=v.y;  v = sp[1]; s1P[2]=v.x; s1P[3]=v.y;
            v = sp[2]; s1P[4]=v.x; s1P[5]=v.y;  v = sp[3]; s1P[6]=v.x; s1P[7]=v.y;
        }

        // start = s1 @ w2.T + b2 (no leaky), replicate into svP
        {
            u64 pt = 0ULL, qt = 0ULL;
#pragma unroll
            for (int k = 0; k < 8; k += 2){
                pt = fma2(w2r[k],   s1P[k],   pt);
                qt = fma2(w2r[k+1], s1P[k+1], qt);
            }
            float at = hb2 + hsum2(add2(pt, qt));
            if (!half) svbuf[g] = at;
        }
        __syncwarp();
        {
            const ulonglong2* sp = reinterpret_cast<const ulonglong2*>(svbuf);
            ulonglong2 v;
            v = sp[0]; svP[0]=v.x; svP[1]=v.y;  v = sp[1]; svP[2]=v.x; svP[3]=v.y;
            v = sp[2]; svP[4]=v.x; svP[5]=v.y;  v = sp[3]; svP[6]=v.x; svP[7]=v.y;
        }
    }
}

// ---------------------------------------------------------------------------
extern "C" void kernel_launch(void* const* d_in, const int* in_sizes, int n_in,
                              void* d_out, int out_size)
{
    const float* seq     = (const float*)d_in[0];
    const float* pre_w1  = (const float*)d_in[1];
    const float* pre_b1  = (const float*)d_in[2];
    const float* pre_w2  = (const float*)d_in[3];
    const float* pre_b2  = (const float*)d_in[4];
    const float* pre_w3  = (const float*)d_in[5];
    const float* pre_b3  = (const float*)d_in[6];
    const float* enc_Wih = (const float*)d_in[7];
    const float* enc_Whh = (const float*)d_in[8];
    const float* enc_bih = (const float*)d_in[9];
    const float* enc_bhh = (const float*)d_in[10];
    const float* h2l_w1  = (const float*)d_in[11];
    const float* h2l_b1  = (const float*)d_in[12];
    const float* h2l_w2  = (const float*)d_in[13];
    const float* h2l_b2  = (const float*)d_in[14];
    const float* post_w  = (const float*)d_in[15];
    const float* post_b  = (const float*)d_in[16];

    int dup = (out_size >= 2 * BB * TT * DD) ? 1 : 0;

    prenet_kernel<<<(BB*TT/2)/256, 256>>>(seq, pre_w1, pre_b1, pre_w2, pre_b2, pre_w3, pre_b3);
    encoder_kernel<<<BB, 32>>>(enc_Wih, enc_Whh, enc_bih, enc_bhh);
    decoder_kernel<<<BB, 32>>>(enc_Wih, enc_Whh, enc_bih, enc_bhh,
                               h2l_w1, h2l_b1, h2l_w2, h2l_b2,
                               post_w, post_b, (float*)d_out, dup);
}

// round 8
// speedup vs baseline: 1.0433x; 1.0357x over previous
#include <cuda_runtime.h>

#define BB 2048
#define TT 512
#define DD 32
#define HH 16
typedef unsigned long long u64;

// Scratch (device globals: allocation-guard-safe)
__device__ __align__(16) float g_x[(size_t)TT * BB * HH];   // pre-net output, [t][b][h]
__device__ __align__(16) float g_h[BB * HH];
__device__ __align__(16) float g_c[BB * HH];

__device__ __forceinline__ float ex2f_(float x){ float y; asm("ex2.approx.f32 %0, %1;" : "=f"(y) : "f"(x)); return y; }
__device__ __forceinline__ float rcpf_(float x){ float y; asm("rcp.approx.f32 %0, %1;" : "=f"(y) : "f"(x)); return y; }

#define L2E 1.4426950408889634f

// v = 1 - m * rcp(1 + 2^(s*x)) : sigmoid (s=L2E,m=1), tanh (s=2*L2E,m=2)
__device__ __forceinline__ float gate_act(float x, float s, float m){
    return fmaf(-m, rcpf_(1.0f + ex2f_(s * x)), 1.0f);
}

// ---- f32x2 packed helpers (FFMA2 is PTX-only; ptxas won't fuse from C++) ----
__device__ __forceinline__ u64 pack2(float lo, float hi){ u64 r; asm("mov.b64 %0, {%1,%2};" : "=l"(r) : "f"(lo), "f"(hi)); return r; }
__device__ __forceinline__ void unpack2(u64 v, float& lo, float& hi){ asm("mov.b64 {%0,%1}, %2;" : "=f"(lo), "=f"(hi) : "l"(v)); }
__device__ __forceinline__ u64 fma2(u64 a, u64 b, u64 c){ u64 d; asm("fma.rn.f32x2 %0, %1, %2, %3;" : "=l"(d) : "l"(a), "l"(b), "l"(c)); return d; }
__device__ __forceinline__ u64 add2(u64 a, u64 b){ u64 d; asm("add.rn.f32x2 %0, %1, %2;" : "=l"(d) : "l"(a), "l"(b)); return d; }
__device__ __forceinline__ float hsum2(u64 a){ float lo, hi; unpack2(a, lo, hi); return lo + hi; }

// ---------------------------------------------------------------------------
// Kernel 1: pre-net. Scalar 1-row/thread (low regs, high occ); weights fetched
// from smem via float4 LDS.128 (4 weights per smem access), dual accumulators.
// ---------------------------------------------------------------------------
__global__ __launch_bounds__(256) void prenet_kernel(
    const float* __restrict__ seq,
    const float* __restrict__ w1, const float* __restrict__ b1,
    const float* __restrict__ w2, const float* __restrict__ b2,
    const float* __restrict__ w3, const float* __restrict__ b3)
{
    __shared__ __align__(16) float sw1[HH*DD];
    __shared__ __align__(16) float sw2[HH*HH];
    __shared__ __align__(16) float sw3[HH*HH];
    __shared__ float sb[3*HH];
    int tid = threadIdx.x;
    for (int i = tid; i < HH*DD; i += 256) sw1[i] = w1[i];
    for (int i = tid; i < HH*HH; i += 256){ sw2[i] = w2[i]; sw3[i] = w3[i]; }
    if (tid < HH){ sb[tid] = b1[tid]; sb[HH+tid] = b2[tid]; sb[2*HH+tid] = b3[tid]; }
    __syncthreads();

    int row = blockIdx.x * 256 + tid;       // row in [0, B*T)
    int b = row & (BB - 1);
    int t = row >> 11;                      // B = 2^11

    const float4* sp = reinterpret_cast<const float4*>(seq) + ((size_t)b*TT + t)*(DD/4);
    float in[DD];
#pragma unroll
    for (int i = 0; i < DD/4; i++){ float4 v = sp[i]; in[4*i]=v.x; in[4*i+1]=v.y; in[4*i+2]=v.z; in[4*i+3]=v.w; }

    const float4* w1v = reinterpret_cast<const float4*>(sw1);
    const float4* w2v = reinterpret_cast<const float4*>(sw2);
    const float4* w3v = reinterpret_cast<const float4*>(sw3);

    float y1[HH];
#pragma unroll
    for (int j = 0; j < HH; j++){
        float a = sb[j], a2 = 0.0f;
#pragma unroll
        for (int k = 0; k < DD/8; k++){            // 8 weights per iter, 2 LDS.128
            float4 wa = w1v[j*(DD/4) + 2*k];
            float4 wb = w1v[j*(DD/4) + 2*k + 1];
            a  = fmaf(wa.x, in[8*k+0], a);  a2 = fmaf(wa.y, in[8*k+1], a2);
            a  = fmaf(wa.z, in[8*k+2], a);  a2 = fmaf(wa.w, in[8*k+3], a2);
            a  = fmaf(wb.x, in[8*k+4], a);  a2 = fmaf(wb.y, in[8*k+5], a2);
            a  = fmaf(wb.z, in[8*k+6], a);  a2 = fmaf(wb.w, in[8*k+7], a2);
        }
        a += a2;
        y1[j] = fmaxf(a, 0.01f*a);
    }
    float y2[HH];
#pragma unroll
    for (int j = 0; j < HH; j++){
        float a = sb[HH+j], a2 = 0.0f;
#pragma unroll
        for (int k = 0; k < HH/8; k++){
            float4 wa = w2v[j*(HH/4) + 2*k];
            float4 wb = w2v[j*(HH/4) + 2*k + 1];
            a  = fmaf(wa.x, y1[8*k+0], a);  a2 = fmaf(wa.y, y1[8*k+1], a2);
            a  = fmaf(wa.z, y1[8*k+2], a);  a2 = fmaf(wa.w, y1[8*k+3], a2);
            a  = fmaf(wb.x, y1[8*k+4], a);  a2 = fmaf(wb.y, y1[8*k+5], a2);
            a  = fmaf(wb.z, y1[8*k+6], a);  a2 = fmaf(wb.w, y1[8*k+7], a2);
        }
        a += a2;
        y2[j] = fmaxf(a, 0.01f*a);
    }
    float y3[HH];
#pragma unroll
    for (int j = 0; j < HH; j++){
        float a = sb[2*HH+j], a2 = 0.0f;
#pragma unroll
        for (int k = 0; k < HH/8; k++){
            float4 wa = w3v[j*(HH/4) + 2*k];
            float4 wb = w3v[j*(HH/4) + 2*k + 1];
            a  = fmaf(wa.x, y2[8*k+0], a);  a2 = fmaf(wa.y, y2[8*k+1], a2);
            a  = fmaf(wa.z, y2[8*k+2], a);  a2 = fmaf(wa.w, y2[8*k+3], a2);
            a  = fmaf(wb.x, y2[8*k+4], a);  a2 = fmaf(wb.y, y2[8*k+5], a2);
            a  = fmaf(wb.z, y2[8*k+6], a);  a2 = fmaf(wb.w, y2[8*k+7], a2);
        }
        y3[j] = a + a2;                    // NO leaky on layer 3
    }

    float4* xp = reinterpret_cast<float4*>(g_x) + ((size_t)t*BB + b)*(HH/4);
    xp[0] = make_float4(y3[0],  y3[1],  y3[2],  y3[3]);
    xp[1] = make_float4(y3[4],  y3[5],  y3[6],  y3[7]);
    xp[2] = make_float4(y3[8],  y3[9],  y3[10], y3[11]);
    xp[3] = make_float4(y3[12], y3[13], y3[14], y3[15]);
}

// ---------------------------------------------------------------------------
// Kernel 2: encoder LSTM. One warp per batch element, 128-thread CTAs so the
// 4 warps land on all 4 SMSPs (wid%4 — 1-warp CTAs all map to SMSP0!).
// Gate matvecs as k-packed FFMA2; h round-trip via smem, double-buffered.
// ---------------------------------------------------------------------------
__global__ __launch_bounds__(128, 4) void encoder_kernel(
    const float* __restrict__ Wih, const float* __restrict__ Whh,
    const float* __restrict__ bih, const float* __restrict__ bhh)
{
    __shared__ __align__(16) float hb[4][2][HH];
    int tid  = threadIdx.x;
    int w    = tid >> 5, lane = tid & 31;
    int g    = lane & 15, half = lane >> 4;
    int b    = blockIdx.x * 4 + w;

    int r0 = half ? (2*HH + g) : g;          // i (low) / g (high)
    int r1 = half ? (3*HH + g) : (HH + g);   // f (low) / o (high)

    u64 wiP0[8], wiP1[8], whP0[8], whP1[8];
    {
        const ulonglong2* p0 = reinterpret_cast<const ulonglong2*>(Wih + r0*HH);
        const ulonglong2* p1 = reinterpret_cast<const ulonglong2*>(Wih + r1*HH);
        const ulonglong2* q0 = reinterpret_cast<const ulonglong2*>(Whh + r0*HH);
        const ulonglong2* q1 = reinterpret_cast<const ulonglong2*>(Whh + r1*HH);
#pragma unroll
        for (int i = 0; i < 4; i++){
            ulonglong2 v;
            v = p0[i]; wiP0[2*i] = v.x; wiP0[2*i+1] = v.y;
            v = p1[i]; wiP1[2*i] = v.x; wiP1[2*i+1] = v.y;
            v = q0[i]; whP0[2*i] = v.x; whP0[2*i+1] = v.y;
            v = q1[i]; whP1[2*i] = v.x; whP1[2*i+1] = v.y;
        }
    }
    u64 bg0P = pack2(bih[r0] + bhh[r0], 0.0f);
    u64 bg1P = pack2(bih[r1] + bhh[r1], 0.0f);
    float s0 = half ? 2.0f*L2E : L2E;
    float m0 = half ? 2.0f : 1.0f;

    u64 hP[8];
#pragma unroll
    for (int k = 0; k < 8; k++) hP[k] = 0ULL;
    float c = 0.0f, h = 0.0f;

    u64 xP[8];
    {
        const ulonglong2* p = reinterpret_cast<const ulonglong2*>(g_x + (size_t)b*HH);
        ulonglong2 v;
        v = p[0]; xP[0]=v.x; xP[1]=v.y;  v = p[1]; xP[2]=v.x; xP[3]=v.y;
        v = p[2]; xP[4]=v.x; xP[5]=v.y;  v = p[3]; xP[6]=v.x; xP[7]=v.y;
    }

#pragma unroll 1
    for (int t = 0; t < TT; t++){
        u64 pA = bg0P, qA = 0ULL, pB = bg1P, qB = 0ULL;
#pragma unroll
        for (int k = 0; k < 8; k += 2){
            pA = fma2(wiP0[k],   xP[k],   pA);
            qA = fma2(wiP0[k+1], xP[k+1], qA);
            pB = fma2(wiP1[k],   xP[k],   pB);
            qB = fma2(wiP1[k+1], xP[k+1], qB);
            pA = fma2(whP0[k],   hP[k],   pA);
            qA = fma2(whP0[k+1], hP[k+1], qA);
            pB = fma2(whP1[k],   hP[k],   pB);
            qB = fma2(whP1[k+1], hP[k+1], qB);
        }
        // prefetch next x (L2-resident) — xP dead after the accum above
        {
            int tn = (t + 1 < TT) ? t + 1 : t;
            const ulonglong2* pn = reinterpret_cast<const ulonglong2*>(g_x + ((size_t)tn*BB + b)*HH);
            ulonglong2 v;
            v = pn[0]; xP[0]=v.x; xP[1]=v.y;  v = pn[1]; xP[2]=v.x; xP[3]=v.y;
            v = pn[2]; xP[4]=v.x; xP[5]=v.y;  v = pn[3]; xP[6]=v.x; xP[7]=v.y;
        }
        float a0 = hsum2(add2(pA, qA));
        float a1 = hsum2(add2(pB, qB));
        float v0 = gate_act(a0, s0, m0);          // i / g
        float v1 = gate_act(a1, L2E, 1.0f);       // f / o
        float gg = __shfl_xor_sync(0xffffffffu, v0, 16);
        float oo = __shfl_xor_sync(0xffffffffu, v1, 16);
        c = fmaf(v1, c, v0 * gg);
        float th = gate_act(c, 2.0f*L2E, 2.0f);
        h = oo * th;

        int ph = t & 1;
        if (!half) hb[w][ph][g] = h;
        __syncwarp();
        {
            const ulonglong2* hp = reinterpret_cast<const ulonglong2*>(hb[w][ph]);
            ulonglong2 v;
            v = hp[0]; hP[0]=v.x; hP[1]=v.y;  v = hp[1]; hP[2]=v.x; hP[3]=v.y;
            v = hp[2]; hP[4]=v.x; hP[5]=v.y;  v = hp[3]; hP[6]=v.x; hP[7]=v.y;
        }
    }
    if (!half){ g_h[b*HH + g] = h; g_c[b*HH + g] = c; }
}

// ---------------------------------------------------------------------------
// Kernel 3: decoder. 128-thread CTAs (SMSP-balanced). k-packed FFMA2 for all
// four matvecs; h2l/post weights in smem as k-packed u64, stride 9 (conflict-
// free). 3 syncwarps/step.
// ---------------------------------------------------------------------------
__global__ __launch_bounds__(128, 4) void decoder_kernel(
    const float* __restrict__ Wih, const float* __restrict__ Whh,
    const float* __restrict__ bih, const float* __restrict__ bhh,
    const float* __restrict__ h2l_w1, const float* __restrict__ h2l_b1,
    const float* __restrict__ h2l_w2, const float* __restrict__ h2l_b2,
    const float* __restrict__ post_w, const float* __restrict__ post_b,
    float* __restrict__ out, int dup)
{
    __shared__ __align__(16) u64 w1p[HH*9];      // {w1[j][2k],w1[j][2k+1]} at [j*9+k]
    __shared__ __align__(16) u64 w2p[HH*9];
    __shared__ __align__(16) u64 postp[DD*9];    // {pw[d][2k],pw[d][2k+1]} at [d*9+k]
    __shared__ __align__(16) float hbuf[4][HH];
    __shared__ __align__(16) float s1buf[4][HH];
    __shared__ __align__(16) float svbuf[4][HH];

    int tid = threadIdx.x;
    for (int i = tid; i < HH*8; i += 128){
        int j = i >> 3, k = i & 7;
        w1p[j*9+k] = pack2(h2l_w1[j*HH+2*k], h2l_w1[j*HH+2*k+1]);
        w2p[j*9+k] = pack2(h2l_w2[j*HH+2*k], h2l_w2[j*HH+2*k+1]);
    }
    for (int i = tid; i < DD*8; i += 128){
        int d = i >> 3, k = i & 7;
        postp[d*9+k] = pack2(post_w[d*HH+2*k], post_w[d*HH+2*k+1]);
    }
    __syncthreads();

    int w    = tid >> 5, lane = tid & 31;
    int g    = lane & 15, half = lane >> 4;
    int b    = blockIdx.x * 4 + w;

    int r0 = half ? (2*HH + g) : g;
    int r1 = half ? (3*HH + g) : (HH + g);

    u64 wiP0[8], wiP1[8], whP0[8], whP1[8];
    {
        const ulonglong2* p0 = reinterpret_cast<const ulonglong2*>(Wih + r0*HH);
        const ulonglong2* p1 = reinterpret_cast<const ulonglong2*>(Wih + r1*HH);
        const ulonglong2* q0 = reinterpret_cast<const ulonglong2*>(Whh + r0*HH);
        const ulonglong2* q1 = reinterpret_cast<const ulonglong2*>(Whh + r1*HH);
#pragma unroll
        for (int i = 0; i < 4; i++){
            ulonglong2 v;
            v = p0[i]; wiP0[2*i] = v.x; wiP0[2*i+1] = v.y;
            v = p1[i]; wiP1[2*i] = v.x; wiP1[2*i+1] = v.y;
            v = q0[i]; whP0[2*i] = v.x; whP0[2*i+1] = v.y;
            v = q1[i]; whP1[2*i] = v.x; whP1[2*i+1] = v.y;
        }
    }
    u64 bg0P = pack2(bih[r0] + bhh[r0], 0.0f);
    u64 bg1P = pack2(bih[r1] + bhh[r1], 0.0f);
    float s0 = half ? 2.0f*L2E : L2E;
    float m0 = half ? 2.0f : 1.0f;
    float pb  = post_b[lane];
    float hb1 = h2l_b1[g];
    float hb2 = h2l_b2[g];

    float c = g_c[b*HH + g];
    u64 hP[8], svP[8];
    {
        const ulonglong2* hp = reinterpret_cast<const ulonglong2*>(g_h + b*HH);
        ulonglong2 v;
        v = hp[0]; hP[0]=v.x; hP[1]=v.y;  v = hp[1]; hP[2]=v.x; hP[3]=v.y;
        v = hp[2]; hP[4]=v.x; hP[5]=v.y;  v = hp[3]; hP[6]=v.x; hP[7]=v.y;
        const ulonglong2* xp = reinterpret_cast<const ulonglong2*>(g_x + ((size_t)(TT-1)*BB + b)*HH);
        v = xp[0]; svP[0]=v.x; svP[1]=v.y;  v = xp[1]; svP[2]=v.x; svP[3]=v.y;
        v = xp[2]; svP[4]=v.x; svP[5]=v.y;  v = xp[3]; svP[6]=v.x; svP[7]=v.y;
    }

    float* outp = out + (size_t)b*TT*DD + lane;
    const size_t dupoff = (size_t)BB*TT*DD;
    const u64* w1r = &w1p[g*9];
    const u64* w2r = &w2p[g*9];
    const u64* pwr = &postp[lane*9];

#pragma unroll 1
    for (int s = 0; s < TT; s++){
        // LSTM gates from (svP, hP)
        u64 pA = bg0P, qA = 0ULL, pB = bg1P, qB = 0ULL;
#pragma unroll
        for (int k = 0; k < 8; k += 2){
            pA = fma2(wiP0[k],   svP[k],   pA);
            qA = fma2(wiP0[k+1], svP[k+1], qA);
            pB = fma2(wiP1[k],   svP[k],   pB);
            qB = fma2(wiP1[k+1], svP[k+1], qB);
            pA = fma2(whP0[k],   hP[k],    pA);
            qA = fma2(whP0[k+1], hP[k+1],  qA);
            pB = fma2(whP1[k],   hP[k],    pB);
            qB = fma2(whP1[k+1], hP[k+1],  qB);
        }
        float a0 = hsum2(add2(pA, qA));
        float a1 = hsum2(add2(pB, qB));
        float v0 = gate_act(a0, s0, m0);
        float v1 = gate_act(a1, L2E, 1.0f);
        float gg = __shfl_xor_sync(0xffffffffu, v0, 16);
        float oo = __shfl_xor_sync(0xffffffffu, v1, 16);
        c = fmaf(v1, c, v0 * gg);
        float th = gate_act(c, 2.0f*L2E, 2.0f);
        float h  = oo * th;

        // replicate h (WAR on hbuf covered by the 3 syncs/step in program order)
        if (!half) hbuf[w][g] = h;
        __syncwarp();
        {
            const ulonglong2* hp = reinterpret_cast<const ulonglong2*>(hbuf[w]);
            ulonglong2 v;
            v = hp[0]; hP[0]=v.x; hP[1]=v.y;  v = hp[1]; hP[2]=v.x; hP[3]=v.y;
            v = hp[2]; hP[4]=v.x; hP[5]=v.y;  v = hp[3]; hP[6]=v.x; hP[7]=v.y;
        }

        // out = h @ post_w.T + post_b  (lane = d)
        {
            u64 po = 0ULL, qo = 0ULL;
#pragma unroll
            for (int k = 0; k < 8; k += 2){
                po = fma2(pwr[k],   hP[k],   po);
                qo = fma2(pwr[k+1], hP[k+1], qo);
            }
            float ao = pb + hsum2(add2(po, qo));
            size_t oidx = (size_t)(TT - 1 - s) * DD;
            outp[oidx] = ao;
            if (dup) outp[oidx + dupoff] = ao;
        }

        // s1 = leaky(h @ w1.T + b1)
        {
            u64 ps = 0ULL, qs = 0ULL;
#pragma unroll
            for (int k = 0; k < 8; k += 2){
                ps = fma2(w1r[k],   hP[k],   ps);
                qs = fma2(w1r[k+1], hP[k+1], qs);
            }
            float as = hb1 + hsum2(add2(ps, qs));
            as = fmaxf(as, 0.01f*as);
            if (!half) s1buf[w][g] = as;
        }
        __syncwarp();
        u64 s1P[8];
        {
            const ulonglong2* sp = reinterpret_cast<const ulonglong2*>(s1buf[w]);
            ulonglong2 v;
            v = sp[0]; s1P[0]=v.x; s1P[1]=v.y;  v = sp[1]; s1P[2]=v.x; s1P[3]=v.y;
            v = sp[2]; s1P[4]=v.x; s1P[5]=v.y;  v = sp[3]; s1P[6]=v.x; s1P[7]=v.y;
        }

        // start = s1 @ w2.T + b2 (no leaky), replicate into svP
        {
            u64 pt = 0ULL, qt = 0ULL;
#pragma unroll
            for (int k = 0; k < 8; k += 2){
                pt = fma2(w2r[k],   s1P[k],   pt);
                qt = fma2(w2r[k+1], s1P[k+1], qt);
            }
            float at = hb2 + hsum2(add2(pt, qt));
            if (!half) svbuf[w][g] = at;
        }
        __syncwarp();
        {
            const ulonglong2* sp = reinterpret_cast<const ulonglong2*>(svbuf[w]);
            ulonglong2 v;
            v = sp[0]; svP[0]=v.x; svP[1]=v.y;  v = sp[1]; svP[2]=v.x; svP[3]=v.y;
            v = sp[2]; svP[4]=v.x; svP[5]=v.y;  v = sp[3]; svP[6]=v.x; svP[7]=v.y;
        }
    }
}

// ---------------------------------------------------------------------------
extern "C" void kernel_launch(void* const* d_in, const int* in_sizes, int n_in,
                              void* d_out, int out_size)
{
    const float* seq     = (const float*)d_in[0];
    const float* pre_w1  = (const float*)d_in[1];
    const float* pre_b1  = (const float*)d_in[2];
    const float* pre_w2  = (const float*)d_in[3];
    const float* pre_b2  = (const float*)d_in[4];
    const float* pre_w3  = (const float*)d_in[5];
    const float* pre_b3  = (const float*)d_in[6];
    const float* enc_Wih = (const float*)d_in[7];
    const float* enc_Whh = (const float*)d_in[8];
    const float* enc_bih = (const float*)d_in[9];
    const float* enc_bhh = (const float*)d_in[10];
    const float* h2l_w1  = (const float*)d_in[11];
    const float* h2l_b1  = (const float*)d_in[12];
    const float* h2l_w2  = (const float*)d_in[13];
    const float* h2l_b2  = (const float*)d_in[14];
    const float* post_w  = (const float*)d_in[15];
    const float* post_b  = (const float*)d_in[16];

    int dup = (out_size >= 2 * BB * TT * DD) ? 1 : 0;

    prenet_kernel<<<(BB*TT)/256, 256>>>(seq, pre_w1, pre_b1, pre_w2, pre_b2, pre_w3, pre_b3);
    encoder_kernel<<<BB/4, 128>>>(enc_Wih, enc_Whh, enc_bih, enc_bhh);
    decoder_kernel<<<BB/4, 128>>>(enc_Wih, enc_Whh, enc_bih, enc_bhh,
                                  h2l_w1, h2l_b1, h2l_w2, h2l_b2,
                                  post_w, post_b, (float*)d_out, dup);
}